// round 11
// baseline (speedup 1.0000x reference)
#include <cuda_runtime.h>

#define WW 512
#define NB 16
#define NPIX (WW * WW)
#define NITERS 10
#define INV_CELL 2.56f        // 1 / (200/512)

// Persistent scratch (no allocations allowed in kernel_launch).
__device__ float  g_tA[NB * NPIX];
__device__ float  g_tB[NB * NPIX];
__device__ float4 g_swv[NB * NPIX];   // (sed, wat, vel, pad)

template <bool FIRST>
__device__ __forceinline__ float tval(float v) {
    return FIRST ? (1.0f - v) * 0.5f : v;
}

// Vertical micro-tile: thread = (column c, rows r0..r0+3); lanes are
// consecutive columns so stencil/state accesses are coalesced and the
// scattered bilinear taps span only ~3 rows x ~2 lines per warp.
template <bool FIRST, bool LAST>
__global__ void __launch_bounds__(256) erosion_step(
    const float* __restrict__ inp,
    const float* __restrict__ rain,
    const float* __restrict__ p_rr,
    const float* __restrict__ p_ev,
    const float* __restrict__ p_mhd,
    const float* __restrict__ p_heps,
    const float* __restrict__ p_grav,
    const float* __restrict__ p_scc,
    const float* __restrict__ p_diss,
    const float* __restrict__ p_depo,
    float* __restrict__ outp,
    int pp)
{
    int c    = blockIdx.x * 256 + threadIdx.x;   // 0..511
    int r0   = blockIdx.y * 4;                   // 0..508
    int base = blockIdx.z * NPIX;

    const float* tin = FIRST ? (inp + base) : ((pp ? g_tB : g_tA) + base);

    // ---- terrain column r0-1 .. r0+4 (row-clamped; clamped rows only feed
    //      boundary formulas that ignore them) ----
    float tcol[6];
    #pragma unroll
    for (int j = 0; j < 6; j++) {
        int gr = min(max(r0 - 1 + j, 0), WW - 1);
        tcol[j] = tval<FIRST>(__ldg(tin + gr * WW + c));
    }

    // ---- horizontal neighbors via warp shuffle + halo loads on edge lanes ----
    float tl[4], trh[4];
    #pragma unroll
    for (int k = 0; k < 4; k++) {
        tl[k]  = __shfl_up_sync(0xffffffffu, tcol[k + 1], 1);
        trh[k] = __shfl_down_sync(0xffffffffu, tcol[k + 1], 1);
    }
    int lane = threadIdx.x & 31;
    if (lane == 0 && c > 0) {
        #pragma unroll
        for (int k = 0; k < 4; k++)
            tl[k] = tval<FIRST>(__ldg(tin + (r0 + k) * WW + (c - 1)));
    }
    if (lane == 31 && c < WW - 1) {
        #pragma unroll
        for (int k = 0; k < 4; k++)
            trh[k] = tval<FIRST>(__ldg(tin + (r0 + k) * WW + (c + 1)));
    }

    // ---- scalar params ----
    float rr   = fmaxf(__ldg(p_rr), 0.0f);
    float ev   = fmaxf(__ldg(p_ev), 0.0f);
    float grav = fmaxf(__ldg(p_grav), 0.0f);
    float heps = 0.0f, mhd = 0.0f, scc = 0.0f, diss = 0.0f, depo = 0.0f;
    if (!FIRST) {
        heps = __ldg(p_heps);
        mhd  = __ldg(p_mhd);
        scc  = fmaxf(__ldg(p_scc), 0.0f);
        diss = __ldg(p_diss);
        depo = __ldg(p_depo);
    }

    // ---- rain + packed state (coalesced, batched for MLP) ----
    float  rn[4];
    float4 st[4];
    #pragma unroll
    for (int k = 0; k < 4; k++) {
        int o = (r0 + k) * WW + c;
        rn[k] = __ldg(rain + o);
        if (!FIRST) st[k] = __ldg(&g_swv[base + o]);
        else        st[k] = make_float4(0.f, 0.f, 0.f, 0.f);
    }

    float* tout = LAST ? nullptr : ((pp ? g_tA : g_tB) + base);

    bool rlo = (r0 == 0);            // block touches top row (k==0 only)
    bool rhi = (r0 == WW - 4);       // block touches bottom row (k==3 only)

    #pragma unroll
    for (int k = 0; k < 4; k++) {
        int   r   = r0 + k;
        int   o   = r * WW + c;
        float t00 = tcol[k + 1];

        float dx;
        if (k == 0 && rlo)      dx = 0.5f * (t00 * 1.1f - t00);
        else if (k == 3 && rhi) dx = 0.5f * (t00 * 0.9f - t00);
        else                    dx = 0.5f * (tcol[k + 2] - tcol[k]);
        float dy = (c == 0)      ? 0.5f * (t00 * 1.1f - t00)
                 : (c == WW - 1) ? 0.5f * (t00 * 0.9f - t00)
                 :                 0.5f * (trh[k] - tl[k]);

        // normalized gradient (factor == 0 always; noise path dead)
        float inv = rsqrtf(dx * dx + dy * dy + 1e-11f);
        float fdx = dx * inv;
        float fdy = dy * inv;

        // bilinear_sample(terrain, -gradient)
        float fx  = (float)c - fdx;
        float fy  = (float)r - fdy;
        float x0f = floorf(fx), y0f = floorf(fy);
        int   x0  = (int)x0f,  y0  = (int)y0f;
        float wx1 = fx - x0f,  wy1 = fy - y0f;

        bool inter = (r >= 1) & (r <= WW - 3) & (c >= 1) & (c <= WW - 3);

        float v00, v10, v01, v11;
        if (inter) {
            const float* p = tin + y0 * WW + x0;
            v00 = tval<FIRST>(__ldg(p))          - 1.0f;
            v10 = tval<FIRST>(__ldg(p + 1))      - 1.0f;
            v01 = tval<FIRST>(__ldg(p + WW))     - 1.0f;
            v11 = tval<FIRST>(__ldg(p + WW + 1)) - 1.0f;
        } else {
            int x1 = x0 + 1, y1 = y0 + 1;
            bool vx0 = (unsigned)x0 < (unsigned)WW;
            bool vx1 = (unsigned)x1 < (unsigned)WW;
            bool vy0 = (unsigned)y0 < (unsigned)WW;
            bool vy1 = (unsigned)y1 < (unsigned)WW;
            int x0c = min(max(x0, 0), WW - 1), x1c = min(max(x1, 0), WW - 1);
            int y0c = min(max(y0, 0), WW - 1), y1c = min(max(y1, 0), WW - 1);
            const float* p0 = tin + y0c * WW;
            const float* p1 = tin + y1c * WW;
            v00 = (vx0 & vy0) ? (tval<FIRST>(__ldg(p0 + x0c)) - 1.0f) : 0.0f;
            v10 = (vx1 & vy0) ? (tval<FIRST>(__ldg(p0 + x1c)) - 1.0f) : 0.0f;
            v01 = (vx0 & vy1) ? (tval<FIRST>(__ldg(p1 + x0c)) - 1.0f) : 0.0f;
            v11 = (vx1 & vy1) ? (tval<FIRST>(__ldg(p1 + x1c)) - 1.0f) : 0.0f;
        }
        float nbv = (1.0f - wy1) * ((1.0f - wx1) * v00 + wx1 * v10)
                  + wy1 * ((1.0f - wx1) * v01 + wx1 * v11) + 1.0f;
        float hd = t00 - nbv;

        if (FIRST) {
            // iter 0: sed == vel == 0 => dep == 0; terrain unchanged.
            float w = rr * rn[k];
            float m1 = fmaxf(-fdy, 0.0f); if (c == WW - 1) m1 = 0.0f;
            float m2 = fmaxf(1.0f - fabsf(fdy), 0.0f);
            float m3 = fmaxf(fdy, 0.0f);  if (c == 0)      m3 = 0.0f;
            w = (m1 * w + m2 * w) + m3 * w;
            tout[o] = t00;
            g_swv[base + o] = make_float4(0.0f, w * (1.0f - ev),
                                          grav * hd * INV_CELL, 0.0f);
        } else {
            float s = st[k].x;
            float w = st[k].y + rr * rn[k];
            float v = st[k].z;

            float hds     = (hd - heps > 0.0f) ? 1.0f : 0.0f;
            float nhd     = hds * fmaxf(hd, mhd);
            float sed_cap = (nhd * INV_CELL) * v * w * scc;
            float ftb     = (hd < 0.0f) ? 1.0f : 0.0f;
            float first   = fminf(fmaxf(-hd, 0.0f), s);
            float sdiff   = s - sed_cap;
            float third   = (1.0f - ftb) *
                            (fmaxf(sdiff * depo, 0.0f) - fmaxf(-sdiff * diss, 0.0f));
            float dep     = fmaxf(-fmaxf(hd, 0.0f), first + third);

            float tnew = t00 + dep;
            if (LAST) {
                outp[base + o] = fmaxf(1.0f + (1.0f - tnew * 2.0f), 0.0f) - 1.0f;
            } else {
                s = s - dep;
                float m1 = fmaxf(-fdy, 0.0f); if (c == WW - 1) m1 = 0.0f;
                float m2 = fmaxf(1.0f - fabsf(fdy), 0.0f);
                float m3 = fmaxf(fdy, 0.0f);  if (c == 0)      m3 = 0.0f;
                s = (m1 * s + m2 * s) + m3 * s;
                w = (m1 * w + m2 * w) + m3 * w;
                tout[o] = tnew;
                g_swv[base + o] = make_float4(s, w * (1.0f - ev),
                                              grav * hd * INV_CELL, 0.0f);
            }
        }
    }
}

extern "C" void kernel_launch(void* const* d_in, const int* in_sizes, int n_in,
                              void* d_out, int out_size) {
    const float* inp      = (const float*)d_in[0];
    const float* rainfall = (const float*)d_in[1];
    // d_in[2] = random_gradient: mathematically dead (factor == 0 always)
    const float* p_rr   = (const float*)d_in[3];
    const float* p_ev   = (const float*)d_in[4];
    const float* p_mhd  = (const float*)d_in[5];
    const float* p_heps = (const float*)d_in[6];
    const float* p_grav = (const float*)d_in[7];
    const float* p_scc  = (const float*)d_in[8];
    const float* p_diss = (const float*)d_in[9];
    const float* p_depo = (const float*)d_in[10];
    float* outp = (float*)d_out;

    dim3 grid(WW / 256, WW / 4, NB);   // (2, 128, 16)
    dim3 block(256);

    for (int it = 0; it < NITERS; ++it) {
        const float* rain = rainfall + it * NPIX;
        int pp = it & 1;
        if (it == 0) {
            erosion_step<true, false><<<grid, block>>>(
                inp, rain, p_rr, p_ev, p_mhd, p_heps, p_grav, p_scc, p_diss,
                p_depo, outp, pp);
        } else if (it == NITERS - 1) {
            erosion_step<false, true><<<grid, block>>>(
                inp, rain, p_rr, p_ev, p_mhd, p_heps, p_grav, p_scc, p_diss,
                p_depo, outp, pp);
        } else {
            erosion_step<false, false><<<grid, block>>>(
                inp, rain, p_rr, p_ev, p_mhd, p_heps, p_grav, p_scc, p_diss,
                p_depo, outp, pp);
        }
    }
}

// round 15
// speedup vs baseline: 1.2453x; 1.2453x over previous
#include <cuda_runtime.h>

#define WW 512
#define NB 16
#define NPIX (WW * WW)
#define NITERS 10
#define INV_CELL 2.56f        // 1 / (200/512)

// Persistent scratch state (no allocations allowed in kernel_launch).
__device__ float g_tA[NB * NPIX];
__device__ float g_tB[NB * NPIX];
__device__ float g_sed[NB * NPIX];
__device__ float g_wat[NB * NPIX];
__device__ float g_vel[NB * NPIX];

template <bool FIRST>
__device__ __forceinline__ float tval(float v) {
    return FIRST ? (1.0f - v) * 0.5f : v;
}

// Thread = 4 horizontal cells. All terrain access (stencil AND bilinear taps)
// comes from a 3x6 register window: since |fdx|,|fdy| < 1 strictly, the 4
// bilinear taps always lie in the 3x3 neighborhood (floor rounding to +1 only
// happens with tap weight exactly 0, where we reuse a finite register).
template <bool FIRST, bool LAST>
__global__ void __launch_bounds__(256) erosion_step(
    const float* __restrict__ inp,
    const float* __restrict__ rain,
    const float* __restrict__ p_rr,
    const float* __restrict__ p_ev,
    const float* __restrict__ p_mhd,
    const float* __restrict__ p_heps,
    const float* __restrict__ p_grav,
    const float* __restrict__ p_scc,
    const float* __restrict__ p_diss,
    const float* __restrict__ p_depo,
    float* __restrict__ outp,
    int pp)
{
    int tid  = blockIdx.x * blockDim.x + threadIdx.x;   // 0 .. NPIX/4-1
    int b    = blockIdx.y;
    int base = b * NPIX;
    int c4   = (tid & 127) << 2;
    int r    = tid >> 7;
    int rowo = r * WW + c4;

    const float* tin = FIRST ? (inp + base) : ((pp ? g_tB : g_tA) + base);

    int rU = max(r - 1, 0), rD = min(r + 1, WW - 1);
    int cL = max(c4 - 1, 0), cR = min(c4 + 4, WW - 1);

    // ---- 3x6 register window (rows rU, r, rD x cols c4-1 .. c4+4) ----
    float U[6], C[6], D[6];
    {
        float4 u4 = __ldg((const float4*)(tin + rU * WW + c4));
        float4 c4v = __ldg((const float4*)(tin + r  * WW + c4));
        float4 d4 = __ldg((const float4*)(tin + rD * WW + c4));
        U[1] = tval<FIRST>(u4.x); U[2] = tval<FIRST>(u4.y);
        U[3] = tval<FIRST>(u4.z); U[4] = tval<FIRST>(u4.w);
        C[1] = tval<FIRST>(c4v.x); C[2] = tval<FIRST>(c4v.y);
        C[3] = tval<FIRST>(c4v.z); C[4] = tval<FIRST>(c4v.w);
        D[1] = tval<FIRST>(d4.x); D[2] = tval<FIRST>(d4.y);
        D[3] = tval<FIRST>(d4.z); D[4] = tval<FIRST>(d4.w);
        U[0] = tval<FIRST>(__ldg(tin + rU * WW + cL));
        C[0] = tval<FIRST>(__ldg(tin + r  * WW + cL));
        D[0] = tval<FIRST>(__ldg(tin + rD * WW + cL));
        U[5] = tval<FIRST>(__ldg(tin + rU * WW + cR));
        C[5] = tval<FIRST>(__ldg(tin + r  * WW + cR));
        D[5] = tval<FIRST>(__ldg(tin + rD * WW + cR));
    }

    // ---- scalar params ----
    float rr   = fmaxf(__ldg(p_rr), 0.0f);
    float ev   = fmaxf(__ldg(p_ev), 0.0f);
    float grav = fmaxf(__ldg(p_grav), 0.0f);
    float heps = 0.0f, mhd = 0.0f, scc = 0.0f, diss = 0.0f, depo = 0.0f;
    if (!FIRST) {
        heps = __ldg(p_heps);
        mhd  = __ldg(p_mhd);
        scc  = fmaxf(__ldg(p_scc), 0.0f);
        diss = __ldg(p_diss);
        depo = __ldg(p_depo);
    }

    float4 rn4 = __ldg((const float4*)(rain + rowo));
    const float* pRn = &rn4.x;

    float4 s4 = make_float4(0.f,0.f,0.f,0.f);
    float4 w4 = make_float4(0.f,0.f,0.f,0.f);
    float4 v4 = make_float4(0.f,0.f,0.f,0.f);
    if (!FIRST) {
        s4 = __ldg((const float4*)(g_sed + base + rowo));
        w4 = __ldg((const float4*)(g_wat + base + rowo));
        v4 = __ldg((const float4*)(g_vel + base + rowo));
    }
    const float* pSi = &s4.x; const float* pWi = &w4.x; const float* pVi = &v4.x;

    float4 oT, oS, oW, oV;
    float* pT = &oT.x; float* pS = &oS.x; float* pW = &oW.x; float* pV = &oV.x;

    #pragma unroll
    for (int i = 0; i < 4; i++) {
        int   c   = c4 + i;
        float t00 = C[i + 1];

        float dx = (r == 0)      ? 0.5f * (t00 * 1.1f - t00)
                 : (r == WW - 1) ? 0.5f * (t00 * 0.9f - t00)
                 :                 0.5f * (D[i + 1] - U[i + 1]);
        float dy = (c == 0)      ? 0.5f * (t00 * 1.1f - t00)
                 : (c == WW - 1) ? 0.5f * (t00 * 0.9f - t00)
                 :                 0.5f * (C[i + 2] - C[i]);

        // normalized gradient (factor == 0 always; noise path dead)
        float inv = rsqrtf(dx * dx + dy * dy + 1e-11f);
        float fdx = dx * inv;
        float fdy = dy * inv;

        // bilinear_sample(terrain, -gradient): weights exactly like reference
        float fx  = (float)c - fdx;
        float fy  = (float)r - fdy;
        float x0f = floorf(fx), y0f = floorf(fy);
        float wx1 = fx - x0f,  wy1 = fy - y0f;
        int   ix0 = (int)x0f - c;   // in {-1, 0, +1}; +1 only with wx1 == 0
        int   iy0 = (int)y0f - r;

        bool sxL = ix0 < 0, sx0 = ix0 == 0;
        bool syT = iy0 < 0, sy0 = iy0 == 0;

        // row-select the 3-col subwindow (top = y0's row, bottom = y0+1's row)
        float tA0 = syT ? U[i]     : (sy0 ? C[i]     : D[i]);
        float tA1 = syT ? U[i + 1] : (sy0 ? C[i + 1] : D[i + 1]);
        float tA2 = syT ? U[i + 2] : (sy0 ? C[i + 2] : D[i + 2]);
        float bA0 = syT ? C[i]     : D[i];      // iy0==+1 -> weight 0, reuse D
        float bA1 = syT ? C[i + 1] : D[i + 1];
        float bA2 = syT ? C[i + 2] : D[i + 2];

        // column-select taps (ix0==+1 -> right tap weight 0, reuse col i+2)
        float v00 = sxL ? tA0 : (sx0 ? tA1 : tA2);
        float v10 = sxL ? tA1 : tA2;
        float v01 = sxL ? bA0 : (sx0 ? bA1 : bA2);
        float v11 = sxL ? bA1 : bA2;

        // validity masks (domain border taps -> 0, matching reference gather)
        int  xL = c + ix0,  yT = r + iy0;
        bool vxL = (unsigned)xL       < (unsigned)WW;
        bool vxR = (unsigned)(xL + 1) < (unsigned)WW;
        bool vyT = (unsigned)yT       < (unsigned)WW;
        bool vyB = (unsigned)(yT + 1) < (unsigned)WW;
        v00 = (vxL & vyT) ? v00 - 1.0f : 0.0f;
        v10 = (vxR & vyT) ? v10 - 1.0f : 0.0f;
        v01 = (vxL & vyB) ? v01 - 1.0f : 0.0f;
        v11 = (vxR & vyB) ? v11 - 1.0f : 0.0f;

        float nbv = (1.0f - wy1) * ((1.0f - wx1) * v00 + wx1 * v10)
                  + wy1 * ((1.0f - wx1) * v01 + wx1 * v11) + 1.0f;
        float hd = t00 - nbv;

        if (FIRST) {
            // iter 0: sed == vel == 0 => dep == 0; terrain unchanged.
            float w = rr * pRn[i];
            float m1 = fmaxf(-fdy, 0.0f); if (c == WW - 1) m1 = 0.0f;
            float m2 = fmaxf(1.0f - fabsf(fdy), 0.0f);
            float m3 = fmaxf(fdy, 0.0f);  if (c == 0)      m3 = 0.0f;
            w = (m1 * w + m2 * w) + m3 * w;
            pT[i] = t00;
            pS[i] = 0.0f;
            pW[i] = w * (1.0f - ev);
            pV[i] = grav * hd * INV_CELL;
        } else {
            float s = pSi[i];
            float w = pWi[i] + rr * pRn[i];
            float v = pVi[i];

            float hds     = (hd - heps > 0.0f) ? 1.0f : 0.0f;
            float nhd     = hds * fmaxf(hd, mhd);
            float sed_cap = (nhd * INV_CELL) * v * w * scc;
            float ftb     = (hd < 0.0f) ? 1.0f : 0.0f;
            float first   = fminf(fmaxf(-hd, 0.0f), s);
            float sdiff   = s - sed_cap;
            float third   = (1.0f - ftb) *
                            (fmaxf(sdiff * depo, 0.0f) - fmaxf(-sdiff * diss, 0.0f));
            float dep     = fmaxf(-fmaxf(hd, 0.0f), first + third);

            float tnew = t00 + dep;
            if (LAST) {
                pT[i] = fmaxf(1.0f + (1.0f - tnew * 2.0f), 0.0f) - 1.0f;
            } else {
                s = s - dep;
                float m1 = fmaxf(-fdy, 0.0f); if (c == WW - 1) m1 = 0.0f;
                float m2 = fmaxf(1.0f - fabsf(fdy), 0.0f);
                float m3 = fmaxf(fdy, 0.0f);  if (c == 0)      m3 = 0.0f;
                s = (m1 * s + m2 * s) + m3 * s;
                w = (m1 * w + m2 * w) + m3 * w;
                pT[i] = tnew;
                pS[i] = s;
                pW[i] = w * (1.0f - ev);
                pV[i] = grav * hd * INV_CELL;
            }
        }
    }

    if (LAST) {
        *(float4*)(outp + base + rowo) = oT;
    } else {
        float* tout = (pp ? g_tA : g_tB) + base;
        *(float4*)(tout + rowo)         = oT;
        *(float4*)(g_sed + base + rowo) = oS;
        *(float4*)(g_wat + base + rowo) = oW;
        *(float4*)(g_vel + base + rowo) = oV;
    }
}

extern "C" void kernel_launch(void* const* d_in, const int* in_sizes, int n_in,
                              void* d_out, int out_size) {
    const float* inp      = (const float*)d_in[0];
    const float* rainfall = (const float*)d_in[1];
    // d_in[2] = random_gradient: mathematically dead (factor == 0 always)
    const float* p_rr   = (const float*)d_in[3];
    const float* p_ev   = (const float*)d_in[4];
    const float* p_mhd  = (const float*)d_in[5];
    const float* p_heps = (const float*)d_in[6];
    const float* p_grav = (const float*)d_in[7];
    const float* p_scc  = (const float*)d_in[8];
    const float* p_diss = (const float*)d_in[9];
    const float* p_depo = (const float*)d_in[10];
    float* outp = (float*)d_out;

    dim3 grid(NPIX / 4 / 256, NB);
    dim3 block(256);

    for (int it = 0; it < NITERS; ++it) {
        const float* rain = rainfall + it * NPIX;
        int pp = it & 1;
        if (it == 0) {
            erosion_step<true, false><<<grid, block>>>(
                inp, rain, p_rr, p_ev, p_mhd, p_heps, p_grav, p_scc, p_diss,
                p_depo, outp, pp);
        } else if (it == NITERS - 1) {
            erosion_step<false, true><<<grid, block>>>(
                inp, rain, p_rr, p_ev, p_mhd, p_heps, p_grav, p_scc, p_diss,
                p_depo, outp, pp);
        } else {
            erosion_step<false, false><<<grid, block>>>(
                inp, rain, p_rr, p_ev, p_mhd, p_heps, p_grav, p_scc, p_diss,
                p_depo, outp, pp);
        }
    }
}

// round 16
// speedup vs baseline: 1.3706x; 1.1006x over previous
#include <cuda_runtime.h>

#define WW 512
#define NB 16
#define NPIX (WW * WW)
#define NITERS 10
#define INV_CELL 2.56f        // 1 / (200/512)

// Persistent scratch state (no allocations allowed in kernel_launch).
__device__ float g_tA[NB * NPIX];
__device__ float g_tB[NB * NPIX];
__device__ float g_sed[NB * NPIX];
__device__ float g_wat[NB * NPIX];
__device__ float g_vel[NB * NPIX];

template <bool FIRST>
__device__ __forceinline__ float tval(float v) {
    return FIRST ? (1.0f - v) * 0.5f : v;
}

// Thread = 4 horizontal cells; all terrain access (stencil AND bilinear taps)
// served from a 3x6 register window. Bilinear evaluated via separable
// row/column weights: tap validity = rowvalid & colvalid and tapweight =
// rowweight*colweight, so the reference's "-1 on valid taps" folds into
// -(Wr*Wc) and invalid taps are masked by zeroing boundary weights.
template <bool FIRST, bool LAST>
__global__ void __launch_bounds__(256) erosion_step(
    const float* __restrict__ inp,
    const float* __restrict__ rain,
    const float* __restrict__ p_rr,
    const float* __restrict__ p_ev,
    const float* __restrict__ p_mhd,
    const float* __restrict__ p_heps,
    const float* __restrict__ p_grav,
    const float* __restrict__ p_scc,
    const float* __restrict__ p_diss,
    const float* __restrict__ p_depo,
    float* __restrict__ outp,
    int pp)
{
    int tid  = blockIdx.x * blockDim.x + threadIdx.x;   // 0 .. NPIX/4-1
    int b    = blockIdx.y;
    int base = b * NPIX;
    int c4   = (tid & 127) << 2;
    int r    = tid >> 7;
    int rowo = r * WW + c4;

    const float* tin = FIRST ? (inp + base) : ((pp ? g_tB : g_tA) + base);

    int rU = max(r - 1, 0), rD = min(r + 1, WW - 1);
    int cL = max(c4 - 1, 0), cR = min(c4 + 4, WW - 1);

    // ---- 3x6 register window (rows rU, r, rD x cols c4-1 .. c4+4) ----
    float U[6], C[6], D[6];
    {
        float4 u4  = __ldg((const float4*)(tin + rU * WW + c4));
        float4 cc4 = __ldg((const float4*)(tin + r  * WW + c4));
        float4 d4  = __ldg((const float4*)(tin + rD * WW + c4));
        U[1] = tval<FIRST>(u4.x);  U[2] = tval<FIRST>(u4.y);
        U[3] = tval<FIRST>(u4.z);  U[4] = tval<FIRST>(u4.w);
        C[1] = tval<FIRST>(cc4.x); C[2] = tval<FIRST>(cc4.y);
        C[3] = tval<FIRST>(cc4.z); C[4] = tval<FIRST>(cc4.w);
        D[1] = tval<FIRST>(d4.x);  D[2] = tval<FIRST>(d4.y);
        D[3] = tval<FIRST>(d4.z);  D[4] = tval<FIRST>(d4.w);
        U[0] = tval<FIRST>(__ldg(tin + rU * WW + cL));
        C[0] = tval<FIRST>(__ldg(tin + r  * WW + cL));
        D[0] = tval<FIRST>(__ldg(tin + rD * WW + cL));
        U[5] = tval<FIRST>(__ldg(tin + rU * WW + cR));
        C[5] = tval<FIRST>(__ldg(tin + r  * WW + cR));
        D[5] = tval<FIRST>(__ldg(tin + rD * WW + cR));
    }

    // ---- scalar params ----
    float rr   = fmaxf(__ldg(p_rr), 0.0f);
    float ev   = fmaxf(__ldg(p_ev), 0.0f);
    float grav = fmaxf(__ldg(p_grav), 0.0f);
    float heps = 0.0f, mhd = 0.0f, scc = 0.0f, diss = 0.0f, depo = 0.0f;
    if (!FIRST) {
        heps = __ldg(p_heps);
        mhd  = __ldg(p_mhd);
        scc  = fmaxf(__ldg(p_scc), 0.0f);
        diss = __ldg(p_diss);
        depo = __ldg(p_depo);
    }

    float4 rn4 = __ldg((const float4*)(rain + rowo));
    const float* pRn = &rn4.x;

    float4 s4 = make_float4(0.f,0.f,0.f,0.f);
    float4 w4 = make_float4(0.f,0.f,0.f,0.f);
    float4 v4 = make_float4(0.f,0.f,0.f,0.f);
    if (!FIRST) {
        s4 = __ldg((const float4*)(g_sed + base + rowo));
        w4 = __ldg((const float4*)(g_wat + base + rowo));
        v4 = __ldg((const float4*)(g_vel + base + rowo));
    }
    const float* pSi = &s4.x; const float* pWi = &w4.x; const float* pVi = &v4.x;

    float4 oT, oS, oW, oV;
    float* pT = &oT.x; float* pS = &oS.x; float* pW = &oW.x; float* pV = &oV.x;

    float rF = (float)r;
    bool rTop = (r == 0), rBot = (r == WW - 1);

    #pragma unroll
    for (int i = 0; i < 4; i++) {
        int   c   = c4 + i;
        float t00 = C[i + 1];

        float dx = rTop ? 0.5f * (t00 * 1.1f - t00)
                 : rBot ? 0.5f * (t00 * 0.9f - t00)
                 :        0.5f * (D[i + 1] - U[i + 1]);
        float dy = (c == 0)      ? 0.5f * (t00 * 1.1f - t00)
                 : (c == WW - 1) ? 0.5f * (t00 * 0.9f - t00)
                 :                 0.5f * (C[i + 2] - C[i]);

        // normalized gradient (factor == 0 always; noise path dead)
        float inv = rsqrtf(dx * dx + dy * dy + 1e-11f);
        float fdx = dx * inv;
        float fdy = dy * inv;

        // bilinear_sample via separable weights over the 3x3 window
        float cF  = (float)c;
        float fx  = cF - fdx;
        float fy  = rF - fdy;
        float x0f = floorf(fx), y0f = floorf(fy);
        float wx1 = fx - x0f,   wy1 = fy - y0f;
        float wxm = 1.0f - wx1, wym = 1.0f - wy1;

        bool sxL = x0f < cF;   // x0 = c-1
        bool sxR = x0f > cF;   // x0 = c+1 (then wx1 == 0)
        bool syT = y0f < rF;
        bool syB = y0f > rF;

        float wL = sxL ? wxm : 0.0f;
        float wC = sxL ? wx1 : (sxR ? 0.0f : wxm);
        float wR = sxL ? 0.0f : (sxR ? wxm : wx1);
        if (c == 0)      wL = 0.0f;   // tap col -1 out of domain
        if (c == WW - 1) wR = 0.0f;   // tap col 512 out of domain

        float wT = syT ? wym : 0.0f;
        float wM = syT ? wy1 : (syB ? 0.0f : wym);
        float wB = syT ? 0.0f : (syB ? wym : wy1);
        if (rTop) wT = 0.0f;
        if (rBot) wB = 0.0f;

        float dotU = wL * U[i] + wC * U[i + 1] + wR * U[i + 2];
        float dotC = wL * C[i] + wC * C[i + 1] + wR * C[i + 2];
        float dotD = wL * D[i] + wC * D[i + 1] + wR * D[i + 2];
        float Wc   = (wL + wC) + wR;
        float Wr   = (wT + wM) + wB;
        float nbv  = (wT * dotU + wM * dotC + wB * dotD) + (1.0f - Wr * Wc);
        float hd   = t00 - nbv;

        if (FIRST) {
            // iter 0: sed == vel == 0 => dep == 0; terrain unchanged.
            float w = rr * pRn[i];
            float m1 = fmaxf(-fdy, 0.0f); if (c == WW - 1) m1 = 0.0f;
            float m2 = fmaxf(1.0f - fabsf(fdy), 0.0f);
            float m3 = fmaxf(fdy, 0.0f);  if (c == 0)      m3 = 0.0f;
            w = w * ((m1 + m2) + m3);
            pT[i] = t00;
            pS[i] = 0.0f;
            pW[i] = w * (1.0f - ev);
            pV[i] = grav * hd * INV_CELL;
        } else {
            float s = pSi[i];
            float w = pWi[i] + rr * pRn[i];
            float v = pVi[i];

            float hds     = (hd - heps > 0.0f) ? 1.0f : 0.0f;
            float nhd     = hds * fmaxf(hd, mhd);
            float sed_cap = (nhd * INV_CELL) * v * w * scc;
            float ftb     = (hd < 0.0f) ? 1.0f : 0.0f;
            float first   = fminf(fmaxf(-hd, 0.0f), s);
            float sdiff   = s - sed_cap;
            float third   = (1.0f - ftb) *
                            (fmaxf(sdiff * depo, 0.0f) - fmaxf(-sdiff * diss, 0.0f));
            float dep     = fmaxf(-fmaxf(hd, 0.0f), first + third);

            float tnew = t00 + dep;
            if (LAST) {
                pT[i] = fmaxf(1.0f + (1.0f - tnew * 2.0f), 0.0f) - 1.0f;
            } else {
                s = s - dep;
                float m1 = fmaxf(-fdy, 0.0f); if (c == WW - 1) m1 = 0.0f;
                float m2 = fmaxf(1.0f - fabsf(fdy), 0.0f);
                float m3 = fmaxf(fdy, 0.0f);  if (c == 0)      m3 = 0.0f;
                float msum = (m1 + m2) + m3;
                pT[i] = tnew;
                pS[i] = s * msum;
                pW[i] = (w * msum) * (1.0f - ev);
                pV[i] = grav * hd * INV_CELL;
            }
        }
    }

    if (LAST) {
        *(float4*)(outp + base + rowo) = oT;
    } else {
        float* tout = (pp ? g_tA : g_tB) + base;
        *(float4*)(tout + rowo)         = oT;
        *(float4*)(g_sed + base + rowo) = oS;
        *(float4*)(g_wat + base + rowo) = oW;
        *(float4*)(g_vel + base + rowo) = oV;
    }
}

extern "C" void kernel_launch(void* const* d_in, const int* in_sizes, int n_in,
                              void* d_out, int out_size) {
    const float* inp      = (const float*)d_in[0];
    const float* rainfall = (const float*)d_in[1];
    // d_in[2] = random_gradient: mathematically dead (factor == 0 always)
    const float* p_rr   = (const float*)d_in[3];
    const float* p_ev   = (const float*)d_in[4];
    const float* p_mhd  = (const float*)d_in[5];
    const float* p_heps = (const float*)d_in[6];
    const float* p_grav = (const float*)d_in[7];
    const float* p_scc  = (const float*)d_in[8];
    const float* p_diss = (const float*)d_in[9];
    const float* p_depo = (const float*)d_in[10];
    float* outp = (float*)d_out;

    dim3 grid(NPIX / 4 / 256, NB);
    dim3 block(256);

    for (int it = 0; it < NITERS; ++it) {
        const float* rain = rainfall + it * NPIX;
        int pp = it & 1;
        if (it == 0) {
            erosion_step<true, false><<<grid, block>>>(
                inp, rain, p_rr, p_ev, p_mhd, p_heps, p_grav, p_scc, p_diss,
                p_depo, outp, pp);
        } else if (it == NITERS - 1) {
            erosion_step<false, true><<<grid, block>>>(
                inp, rain, p_rr, p_ev, p_mhd, p_heps, p_grav, p_scc, p_diss,
                p_depo, outp, pp);
        } else {
            erosion_step<false, false><<<grid, block>>>(
                inp, rain, p_rr, p_ev, p_mhd, p_heps, p_grav, p_scc, p_diss,
                p_depo, outp, pp);
        }
    }
}